// round 1
// baseline (speedup 1.0000x reference)
#include <cuda_runtime.h>
#include <cstddef>

// Problem dims (fixed)
#define B_    4096
#define N0_   2048
#define N1_   1000
#define N2_   500
#define N3_   100
#define C_    100
#define NCLS_ 12
#define NDIM_ 3

// Scratch (allocation-free rule: __device__ globals)
__device__ float g_h1[(size_t)B_ * N1_];
__device__ float g_h2[(size_t)B_ * N2_];
__device__ int   g_idx[B_];

// ---------------------------------------------------------------------------
// Generic tiled SGEMM with bias (+ optional ReLU): C = act(A[M,K] @ W[K,N] + b)
// ---------------------------------------------------------------------------
template<int BM, int BN, int BK, int TM, int TN, bool RELU>
__global__ __launch_bounds__(256, 2)
void gemm_bias(const float* __restrict__ A, const float* __restrict__ W,
               const float* __restrict__ bias, float* __restrict__ Cout,
               int M, int N, int K)
{
    __shared__ float As[BK][BM];
    __shared__ float Bs[BK][BN];
    const int tid = threadIdx.x;
    const int bm = blockIdx.y * BM;
    const int bn = blockIdx.x * BN;
    constexpr int TX = BN / TN;
    const int tx = tid % TX;
    const int ty = tid / TX;

    float acc[TM][TN];
#pragma unroll
    for (int i = 0; i < TM; i++)
#pragma unroll
        for (int j = 0; j < TN; j++) acc[i][j] = 0.f;

    for (int k0 = 0; k0 < K; k0 += BK) {
#pragma unroll
        for (int i = tid; i < BM * BK; i += 256) {
            int m = i / BK, kk = i % BK;
            int gm = bm + m, gk = k0 + kk;
            As[kk][m] = (gm < M && gk < K) ? A[(size_t)gm * K + gk] : 0.f;
        }
#pragma unroll
        for (int i = tid; i < BK * BN; i += 256) {
            int kk = i / BN, n = i % BN;
            int gk = k0 + kk, gn = bn + n;
            Bs[kk][n] = (gk < K && gn < N) ? W[(size_t)gk * N + gn] : 0.f;
        }
        __syncthreads();
#pragma unroll
        for (int kk = 0; kk < BK; kk++) {
            float a[TM], b[TN];
#pragma unroll
            for (int i = 0; i < TM; i++) a[i] = As[kk][ty * TM + i];
#pragma unroll
            for (int j = 0; j < TN; j++) b[j] = Bs[kk][tx * TN + j];
#pragma unroll
            for (int i = 0; i < TM; i++)
#pragma unroll
                for (int j = 0; j < TN; j++)
                    acc[i][j] = fmaf(a[i], b[j], acc[i][j]);
        }
        __syncthreads();
    }

#pragma unroll
    for (int i = 0; i < TM; i++) {
        int gm = bm + ty * TM + i;
        if (gm >= M) continue;
#pragma unroll
        for (int j = 0; j < TN; j++) {
            int gn = bn + tx * TN + j;
            if (gn >= N) continue;
            float v = acc[i][j] + bias[gn];
            if (RELU) v = fmaxf(v, 0.f);
            Cout[(size_t)gm * N + gn] = v;
        }
    }
}

// ---------------------------------------------------------------------------
// Row-wise argmax over y1[B, C] -> idx[B] (first max on ties, like jnp.argmax)
// ---------------------------------------------------------------------------
__global__ void argmax_rows(const float* __restrict__ y1, int* __restrict__ idx)
{
    int b = blockIdx.x * (blockDim.x >> 5) + (threadIdx.x >> 5);
    if (b >= B_) return;
    int lane = threadIdx.x & 31;
    float best = -__int_as_float(0x7f800000);  // -inf
    int bi = C_;
    for (int c = lane; c < C_; c += 32) {
        float v = y1[(size_t)b * C_ + c];
        if (v > best) { best = v; bi = c; }
    }
#pragma unroll
    for (int off = 16; off; off >>= 1) {
        float ov = __shfl_down_sync(0xffffffffu, best, off);
        int   oi = __shfl_down_sync(0xffffffffu, bi, off);
        if (ov > best || (ov == best && oi < bi)) { best = ov; bi = oi; }
    }
    if (lane == 0) idx[b] = bi;
}

// ---------------------------------------------------------------------------
// Per-row: category head y0 (12), selected-expert MLP he(100)->y2(3).
// One CTA of 256 threads per row. x row staged in smem.
// ---------------------------------------------------------------------------
__global__ __launch_bounds__(256)
void expert_cat_kernel(const float* __restrict__ x,
                       const float* __restrict__ Wcat, const float* __restrict__ bcat,
                       const float* __restrict__ We1,  const float* __restrict__ be1,
                       const float* __restrict__ We2,  const float* __restrict__ be2,
                       const int* __restrict__ idx,
                       float* __restrict__ y0, float* __restrict__ y2)
{
    __shared__ float xs[N0_];
    __shared__ float ps[2][128];
    __shared__ float he[128];
    const int b = blockIdx.x;
    const int t = threadIdx.x;

    const float4* xr = reinterpret_cast<const float4*>(x + (size_t)b * N0_);
#pragma unroll
    for (int i = t; i < N0_ / 4; i += 256)
        reinterpret_cast<float4*>(xs)[i] = xr[i];
    __syncthreads();

    const int c = idx[b];

    // ---- category head: 12 outputs x 16-lane reduction groups ----
    {
        int j = t >> 4, s = t & 15;
        int jj = (j < NCLS_) ? j : 0;
        float a = 0.f;
        for (int n = s; n < N0_; n += 16)
            a = fmaf(xs[n], Wcat[(size_t)n * NCLS_ + jj], a);
#pragma unroll
        for (int off = 8; off; off >>= 1)
            a += __shfl_down_sync(0xffffffffu, a, off, 16);
        if (s == 0 && j < NCLS_)
            y0[(size_t)b * NCLS_ + j] = a + bcat[j];
    }

    // ---- selected expert hidden: he[k] = relu(sum_n x[n]*We1[c,n,k] + be1[c,k]) ----
    {
        const int k = t & 127;       // output index (k < 100 active)
        const int s = t >> 7;        // slice 0/1 over parity of n
        const int kk = (k < N3_) ? k : 0;
        const float* W = We1 + (size_t)c * N0_ * N3_ + kk;
        float a0 = 0.f, a1 = 0.f;
        for (int n = s; n < N0_; n += 4) {
            a0 = fmaf(xs[n],     W[(size_t)n * N3_],       a0);
            a1 = fmaf(xs[n + 2], W[(size_t)(n + 2) * N3_], a1);
        }
        ps[s][k] = a0 + a1;
    }
    __syncthreads();
    if (t < N3_) {
        float v = ps[0][t] + ps[1][t] + be1[(size_t)c * N3_ + t];
        he[t] = fmaxf(v, 0.f);
    }
    __syncthreads();

    // ---- y2[d] = sum_k he[k] * We2[c,k,d] + be2[c,d] ----
    if (t < NDIM_) {
        const float* W2 = We2 + (size_t)c * N3_ * NDIM_ + t;
        float a = 0.f;
#pragma unroll 4
        for (int k = 0; k < N3_; k++)
            a = fmaf(he[k], W2[(size_t)k * NDIM_], a);
        y2[(size_t)b * NDIM_ + t] = a + be2[(size_t)c * NDIM_ + t];
    }
}

// ---------------------------------------------------------------------------
extern "C" void kernel_launch(void* const* d_in, const int* in_sizes, int n_in,
                              void* d_out, int out_size)
{
    (void)in_sizes; (void)n_in; (void)out_size;
    const float* x    = (const float*)d_in[0];
    const float* Wcat = (const float*)d_in[1];
    const float* bcat = (const float*)d_in[2];
    const float* Wb1  = (const float*)d_in[3];
    const float* bb1  = (const float*)d_in[4];
    const float* Wb2  = (const float*)d_in[5];
    const float* bb2  = (const float*)d_in[6];
    const float* Wb3  = (const float*)d_in[7];
    const float* bb3  = (const float*)d_in[8];
    const float* We1  = (const float*)d_in[9];
    const float* be1  = (const float*)d_in[10];
    const float* We2  = (const float*)d_in[11];
    const float* be2  = (const float*)d_in[12];

    float* out = (float*)d_out;
    float* y0 = out;
    float* y1 = out + (size_t)B_ * NCLS_;
    float* y2 = out + (size_t)B_ * (NCLS_ + C_);

    float* h1 = nullptr;
    float* h2 = nullptr;
    int*   idx = nullptr;
    cudaGetSymbolAddress((void**)&h1, g_h1);
    cudaGetSymbolAddress((void**)&h2, g_h2);
    cudaGetSymbolAddress((void**)&idx, g_idx);

    // h1 = relu(x @ Wb1 + bb1)          [4096,1000], K=2048
    gemm_bias<128,128,8,8,8,true><<<dim3((N1_+127)/128, B_/128), 256>>>(
        x, Wb1, bb1, h1, B_, N1_, N0_);
    // h2 = relu(h1 @ Wb2 + bb2)         [4096,500], K=1000
    gemm_bias<128,128,8,8,8,true><<<dim3((N2_+127)/128, B_/128), 256>>>(
        h1, Wb2, bb2, h2, B_, N2_, N1_);
    // y1 = h2 @ Wb3 + bb3               [4096,100], K=500
    gemm_bias<64,64,16,4,4,false><<<dim3((C_+63)/64, B_/64), 256>>>(
        h2, Wb3, bb3, y1, B_, C_, N2_);
    // idx = argmax(y1)
    argmax_rows<<<B_/8, 256>>>(y1, idx);
    // y0 + selected-expert y2
    expert_cat_kernel<<<B_, 256>>>(x, Wcat, bcat, We1, be1, We2, be2, idx, y0, y2);
}

// round 3
// speedup vs baseline: 1.0560x; 1.0560x over previous
#include <cuda_runtime.h>
#include <cstddef>

// Problem dims (fixed)
#define B_    4096
#define N0_   2048
#define N1_   1000
#define N2_   500
#define N3_   100
#define C_    100
#define NCLS_ 12
#define NDIM_ 3

#define N1P   1024   // padded h1 width
#define N2P   512    // padded h2 width

// Scratch (allocation-free rule: __device__ globals)
__device__ float g_h1[(size_t)B_ * N1P];
__device__ float g_h2[(size_t)B_ * N2P];
__device__ int   g_idx[B_];
__device__ int   g_cnt[C_];
__device__ int   g_off[C_ + 1];
__device__ int   g_cur[C_];
__device__ int   g_rows[B_];

// ---------------------------------------------------------------------------
// Tiled SGEMM with bias (+ optional ReLU), padded-output support.
//   Cout[M, ldc] = act(A[M, Kpad] @ W[Kreal, Nreal] + bias)
// A is fully padded (rows exact multiple of BM, cols = Kpad, zeros in pad).
// W loads guarded by Kreal (rows) and, in the N-edge block, by Nreal.
// PADZ: write zeros for columns in [Nreal, ldc).
// ---------------------------------------------------------------------------
template<int BM, int BN, int BK, int TM, int TN, bool RELU, bool PADZ>
__global__ __launch_bounds__(256, 2)
void gemm_bias(const float* __restrict__ A, const float* __restrict__ W,
               const float* __restrict__ bias, float* __restrict__ Cout,
               int Nreal, int Kpad, int Kreal, int ldc)
{
    __shared__ float As[BK][BM + 4];
    __shared__ float Bs[BK][BN];
    const int tid = threadIdx.x;
    const int bm = blockIdx.y * BM;
    const int bn = blockIdx.x * BN;
    constexpr int TX = BN / TN;
    const int tx = tid % TX;
    const int ty = tid / TX;
    const bool nedge = (bn + BN > Nreal);

    float acc[TM][TN];
#pragma unroll
    for (int i = 0; i < TM; i++)
#pragma unroll
        for (int j = 0; j < TN; j++) acc[i][j] = 0.f;

    constexpr int AIT = (BM * BK / 4) / 256;
    constexpr int BIT = (BK * BN / 4) / 256;

    for (int k0 = 0; k0 < Kpad; k0 += BK) {
        // --- A tile (no guards: A exact in M, padded in K) ---
#pragma unroll
        for (int s = 0; s < AIT; s++) {
            int f = tid + s * 256;
            int m = f / (BK / 4);
            int k4 = f % (BK / 4);
            float4 v = *reinterpret_cast<const float4*>(
                A + (size_t)(bm + m) * Kpad + k0 + 4 * k4);
            As[4 * k4 + 0][m] = v.x;
            As[4 * k4 + 1][m] = v.y;
            As[4 * k4 + 2][m] = v.z;
            As[4 * k4 + 3][m] = v.w;
        }
        // --- W tile ---
        if (!nedge) {
#pragma unroll
            for (int s = 0; s < BIT; s++) {
                int f = tid + s * 256;
                int kk = f / (BN / 4);
                int n4 = f % (BN / 4);
                int gk = k0 + kk;
                float4 v = make_float4(0.f, 0.f, 0.f, 0.f);
                if (gk < Kreal)
                    v = *reinterpret_cast<const float4*>(
                        W + (size_t)gk * Nreal + bn + 4 * n4);
                *reinterpret_cast<float4*>(&Bs[kk][4 * n4]) = v;
            }
        } else {
            for (int i = tid; i < BK * BN; i += 256) {
                int kk = i / BN, n = i % BN;
                int gk = k0 + kk, gn = bn + n;
                Bs[kk][n] = (gk < Kreal && gn < Nreal)
                            ? W[(size_t)gk * Nreal + gn] : 0.f;
            }
        }
        __syncthreads();
#pragma unroll
        for (int kk = 0; kk < BK; kk++) {
            float a[TM], b[TN];
#pragma unroll
            for (int i = 0; i < TM; i += 4) {
                float4 v = *reinterpret_cast<const float4*>(&As[kk][ty * TM + i]);
                a[i] = v.x; a[i + 1] = v.y; a[i + 2] = v.z; a[i + 3] = v.w;
            }
#pragma unroll
            for (int j = 0; j < TN; j += 4) {
                float4 v = *reinterpret_cast<const float4*>(&Bs[kk][tx * TN + j]);
                b[j] = v.x; b[j + 1] = v.y; b[j + 2] = v.z; b[j + 3] = v.w;
            }
#pragma unroll
            for (int i = 0; i < TM; i++)
#pragma unroll
                for (int j = 0; j < TN; j++)
                    acc[i][j] = fmaf(a[i], b[j], acc[i][j]);
        }
        __syncthreads();
    }

#pragma unroll
    for (int i = 0; i < TM; i++) {
        int gm = bm + ty * TM + i;
#pragma unroll
        for (int j = 0; j < TN; j++) {
            int gn = bn + tx * TN + j;
            float bv = (gn < Nreal) ? bias[gn] : 0.f;
            float v = acc[i][j] + bv;
            if (RELU) v = fmaxf(v, 0.f);
            if (PADZ) {
                if (gn >= Nreal) v = 0.f;
                Cout[(size_t)gm * ldc + gn] = v;
            } else {
                if (gn < Nreal) Cout[(size_t)gm * ldc + gn] = v;
            }
        }
    }
}

// ---------------------------------------------------------------------------
// Row-wise argmax over y1[B, C] -> idx[B] (first max on ties)
// ---------------------------------------------------------------------------
__global__ void argmax_rows(const float* __restrict__ y1, int* __restrict__ idx)
{
    int b = blockIdx.x * (blockDim.x >> 5) + (threadIdx.x >> 5);
    if (b >= B_) return;
    int lane = threadIdx.x & 31;
    float best = -__int_as_float(0x7f800000);
    int bi = C_;
    for (int c = lane; c < C_; c += 32) {
        float v = y1[(size_t)b * C_ + c];
        if (v > best) { best = v; bi = c; }
    }
#pragma unroll
    for (int off = 16; off; off >>= 1) {
        float ov = __shfl_down_sync(0xffffffffu, best, off);
        int   oi = __shfl_down_sync(0xffffffffu, bi, off);
        if (ov > best || (ov == best && oi < bi)) { best = ov; bi = oi; }
    }
    if (lane == 0) idx[b] = bi;
}

// ---------------------------------------------------------------------------
// Sort-by-expert machinery
// ---------------------------------------------------------------------------
__global__ void zero_cnt_k()
{
    int t = threadIdx.x;
    if (t < C_) g_cnt[t] = 0;
}
__global__ void hist_k(const int* __restrict__ idx)
{
    int b = blockIdx.x * 256 + threadIdx.x;
    if (b < B_) atomicAdd(&g_cnt[idx[b]], 1);
}
__global__ void scan_k()
{
    if (threadIdx.x == 0) {
        int a = 0;
        for (int c = 0; c < C_; c++) {
            g_off[c] = a;
            g_cur[c] = a;
            a += g_cnt[c];
        }
        g_off[C_] = a;
    }
}
__global__ void scat_k(const int* __restrict__ idx)
{
    int b = blockIdx.x * 256 + threadIdx.x;
    if (b < B_) {
        int p = atomicAdd(&g_cur[idx[b]], 1);
        g_rows[p] = b;
    }
}

// ---------------------------------------------------------------------------
// Category head: y0 = x @ Wcat + bcat. One warp per row.
// ---------------------------------------------------------------------------
__global__ __launch_bounds__(256)
void cat_head(const float* __restrict__ x, const float* __restrict__ Wcat,
              const float* __restrict__ bcat, float* __restrict__ y0)
{
    int b = blockIdx.x * 8 + (threadIdx.x >> 5);
    int lane = threadIdx.x & 31;
    const float* xr = x + (size_t)b * N0_;
    float acc[NCLS_];
#pragma unroll
    for (int j = 0; j < NCLS_; j++) acc[j] = 0.f;
    for (int n = lane; n < N0_; n += 32) {
        float xv = xr[n];
        const float* wr = Wcat + (size_t)n * NCLS_;
#pragma unroll
        for (int j = 0; j < NCLS_; j++)
            acc[j] = fmaf(xv, wr[j], acc[j]);
    }
#pragma unroll
    for (int j = 0; j < NCLS_; j++) {
#pragma unroll
        for (int off = 16; off; off >>= 1)
            acc[j] += __shfl_down_sync(0xffffffffu, acc[j], off);
    }
    if (lane == 0) {
#pragma unroll
        for (int j = 0; j < NCLS_; j++)
            y0[(size_t)b * NCLS_ + j] = acc[j] + bcat[j];
    }
}

// ---------------------------------------------------------------------------
// Grouped expert kernel: CTA = (expert c, chunk of up to 32 rows of c).
// GEMM  he[32,100] = relu(Xg[32,2048] @ We1[c] + be1[c]); then
// y2[r] = he[r] @ We2[c] + be2[c].
// ---------------------------------------------------------------------------
#define MROWS 32
#define BKE   32

__global__ __launch_bounds__(256)
void expert_group(const float* __restrict__ x,
                  const float* __restrict__ We1, const float* __restrict__ be1,
                  const float* __restrict__ We2, const float* __restrict__ be2,
                  float* __restrict__ y2)
{
    const int c = blockIdx.x;
    const int base = g_off[c] + blockIdx.y * MROWS;
    const int end = g_off[c + 1];
    if (base >= end) return;
    const int nr = min(MROWS, end - base);

    __shared__ float xs[MROWS][BKE];       // 4 KB
    __shared__ float ws[BKE][128];         // 16 KB (cols 100..127 stay zero)
    __shared__ float he[MROWS][104];       // 13 KB
    __shared__ int   rs[MROWS];

    const int tid = threadIdx.x;
    if (tid < MROWS) rs[tid] = (tid < nr) ? g_rows[base + tid] : -1;
    for (int i = tid; i < BKE * 28; i += 256) {
        int kk = i / 28, n = 100 + i % 28;
        ws[kk][n] = 0.f;
    }
    __syncthreads();

    const int tx = tid & 31;   // column group: cols 4*tx..4*tx+3
    const int ty = tid >> 5;   // row group:    rows 4*ty..4*ty+3
    const int r_ld = tid >> 3; // 0..31 (x-tile loader row)
    const int q_ld = tid & 7;  // float4 slot within row segment
    const int row_ld = rs[r_ld];

    float acc[4][4];
#pragma unroll
    for (int i = 0; i < 4; i++)
#pragma unroll
        for (int j = 0; j < 4; j++) acc[i][j] = 0.f;

    const float* Wc = We1 + (size_t)c * (N0_ * N3_);

    for (int k0 = 0; k0 < N0_; k0 += BKE) {
        float4 v = make_float4(0.f, 0.f, 0.f, 0.f);
        if (row_ld >= 0)
            v = reinterpret_cast<const float4*>(x + (size_t)row_ld * N0_ + k0)[q_ld];
        *reinterpret_cast<float4*>(&xs[r_ld][q_ld * 4]) = v;

        for (int i = tid; i < BKE * N3_; i += 256) {
            int kk = i / N3_, n = i - kk * N3_;
            ws[kk][n] = Wc[(size_t)(k0 + kk) * N3_ + n];
        }
        __syncthreads();
#pragma unroll
        for (int kk = 0; kk < BKE; kk++) {
            float4 b4 = *reinterpret_cast<const float4*>(&ws[kk][tx * 4]);
            float a0 = xs[ty * 4 + 0][kk];
            float a1 = xs[ty * 4 + 1][kk];
            float a2 = xs[ty * 4 + 2][kk];
            float a3 = xs[ty * 4 + 3][kk];
            acc[0][0] = fmaf(a0, b4.x, acc[0][0]);
            acc[0][1] = fmaf(a0, b4.y, acc[0][1]);
            acc[0][2] = fmaf(a0, b4.z, acc[0][2]);
            acc[0][3] = fmaf(a0, b4.w, acc[0][3]);
            acc[1][0] = fmaf(a1, b4.x, acc[1][0]);
            acc[1][1] = fmaf(a1, b4.y, acc[1][1]);
            acc[1][2] = fmaf(a1, b4.z, acc[1][2]);
            acc[1][3] = fmaf(a1, b4.w, acc[1][3]);
            acc[2][0] = fmaf(a2, b4.x, acc[2][0]);
            acc[2][1] = fmaf(a2, b4.y, acc[2][1]);
            acc[2][2] = fmaf(a2, b4.z, acc[2][2]);
            acc[2][3] = fmaf(a2, b4.w, acc[2][3]);
            acc[3][0] = fmaf(a3, b4.x, acc[3][0]);
            acc[3][1] = fmaf(a3, b4.y, acc[3][1]);
            acc[3][2] = fmaf(a3, b4.z, acc[3][2]);
            acc[3][3] = fmaf(a3, b4.w, acc[3][3]);
        }
        __syncthreads();
    }

    // bias + relu -> he (only cols < 100, i.e. tx < 25)
    if (tx < 25) {
        float4 bb = *reinterpret_cast<const float4*>(be1 + (size_t)c * N3_ + tx * 4);
#pragma unroll
        for (int i = 0; i < 4; i++) {
            he[ty * 4 + i][tx * 4 + 0] = fmaxf(acc[i][0] + bb.x, 0.f);
            he[ty * 4 + i][tx * 4 + 1] = fmaxf(acc[i][1] + bb.y, 0.f);
            he[ty * 4 + i][tx * 4 + 2] = fmaxf(acc[i][2] + bb.z, 0.f);
            he[ty * 4 + i][tx * 4 + 3] = fmaxf(acc[i][3] + bb.w, 0.f);
        }
    }
    __syncthreads();

    // y2[r, d] = he[r] . We2[c, :, d] + be2[c, d]
    if (tid < MROWS * 4) {
        int r = tid >> 2, d = tid & 3;
        if (r < nr && d < NDIM_) {
            const float* W2 = We2 + (size_t)c * (N3_ * NDIM_) + d;
            float a = 0.f;
#pragma unroll 4
            for (int k = 0; k < N3_; k++)
                a = fmaf(he[r][k], W2[(size_t)k * NDIM_], a);
            y2[(size_t)rs[r] * NDIM_ + d] = a + be2[(size_t)c * NDIM_ + d];
        }
    }
}

// ---------------------------------------------------------------------------
extern "C" void kernel_launch(void* const* d_in, const int* in_sizes, int n_in,
                              void* d_out, int out_size)
{
    (void)in_sizes; (void)n_in; (void)out_size;
    const float* x    = (const float*)d_in[0];
    const float* Wcat = (const float*)d_in[1];
    const float* bcat = (const float*)d_in[2];
    const float* Wb1  = (const float*)d_in[3];
    const float* bb1  = (const float*)d_in[4];
    const float* Wb2  = (const float*)d_in[5];
    const float* bb2  = (const float*)d_in[6];
    const float* Wb3  = (const float*)d_in[7];
    const float* bb3  = (const float*)d_in[8];
    const float* We1  = (const float*)d_in[9];
    const float* be1  = (const float*)d_in[10];
    const float* We2  = (const float*)d_in[11];
    const float* be2  = (const float*)d_in[12];

    float* out = (float*)d_out;
    float* y0 = out;
    float* y1 = out + (size_t)B_ * NCLS_;
    float* y2 = out + (size_t)B_ * (NCLS_ + C_);

    float* h1 = nullptr;
    float* h2 = nullptr;
    int*   idx = nullptr;
    cudaGetSymbolAddress((void**)&h1, g_h1);
    cudaGetSymbolAddress((void**)&h2, g_h2);
    cudaGetSymbolAddress((void**)&idx, g_idx);

    // h1 = relu(x @ Wb1 + bb1), written padded [4096,1024]
    gemm_bias<128, 128, 16, 8, 8, true, true>
        <<<dim3(N1P / 128, B_ / 128), 256>>>(x, Wb1, bb1, h1, N1_, N0_, N0_, N1P);
    // h2 = relu(h1 @ Wb2 + bb2), written padded [4096,512]
    gemm_bias<128, 128, 16, 8, 8, true, true>
        <<<dim3(N2P / 128, B_ / 128), 256>>>(h1, Wb2, bb2, h2, N2_, N1P, N1_, N2P);
    // y1 = h2 @ Wb3 + bb3   [4096,100]
    gemm_bias<64, 128, 16, 4, 8, false, false>
        <<<dim3(1, B_ / 64), 256>>>(h2, Wb3, bb3, y1, C_, N2P, N2_, C_);
    // idx = argmax(y1)
    argmax_rows<<<B_ / 8, 256>>>(y1, idx);
    // group rows by expert
    zero_cnt_k<<<1, 128>>>();
    hist_k<<<B_ / 256, 256>>>(idx);
    scan_k<<<1, 32>>>();
    scat_k<<<B_ / 256, 256>>>(idx);
    // category head
    cat_head<<<B_ / 8, 256>>>(x, Wcat, bcat, y0);
    // grouped expert path
    expert_group<<<dim3(C_, B_ / MROWS), 256>>>(x, We1, be1, We2, be2, y2);
}

// round 6
// speedup vs baseline: 1.6777x; 1.5887x over previous
#include <cuda_runtime.h>
#include <cuda_bf16.h>
#include <cstdint>
#include <cstddef>

// Problem dims (fixed)
#define B_    4096
#define N0_   2048
#define N1_   1000
#define N2_   500
#define N3_   100
#define C_    100
#define NCLS_ 12
#define NDIM_ 3

#define N1P   1024   // padded h1 width
#define N2P   512    // padded h2 width
#define N3P   128    // padded y1 width (tile only)

// ---------------------------------------------------------------------------
// Scratch (allocation-free rule: __device__ globals)
// ---------------------------------------------------------------------------
__device__ __nv_bfloat16 g_xh[(size_t)B_ * N0_];
__device__ __nv_bfloat16 g_xl[(size_t)B_ * N0_];
__device__ __nv_bfloat16 g_w1h[(size_t)N1P * N0_];
__device__ __nv_bfloat16 g_w1l[(size_t)N1P * N0_];
__device__ __nv_bfloat16 g_w2h[(size_t)N2P * N1P];
__device__ __nv_bfloat16 g_w2l[(size_t)N2P * N1P];
__device__ __nv_bfloat16 g_w3h[(size_t)N3P * N2P];
__device__ __nv_bfloat16 g_w3l[(size_t)N3P * N2P];
__device__ __nv_bfloat16 g_h1h[(size_t)B_ * N1P];
__device__ __nv_bfloat16 g_h1l[(size_t)B_ * N1P];
__device__ __nv_bfloat16 g_h2h[(size_t)B_ * N2P];
__device__ __nv_bfloat16 g_h2l[(size_t)B_ * N2P];
__device__ int g_idx[B_];
__device__ int g_cnt[C_];
__device__ int g_off[C_ + 1];
__device__ int g_cur[C_];
__device__ int g_rows[B_];

// ---------------------------------------------------------------------------
// Helpers
// ---------------------------------------------------------------------------
__device__ __forceinline__ uint32_t smem_u32(const void* p) {
    uint32_t a;
    asm("{ .reg .u64 t; cvta.to.shared.u64 t, %1; cvt.u32.u64 %0, t; }"
        : "=r"(a) : "l"(p));
    return a;
}

__device__ __forceinline__ void bf16_split(float v, __nv_bfloat16& h, __nv_bfloat16& l) {
    h = __float2bfloat16_rn(v);
    l = __float2bfloat16_rn(v - __bfloat162float(h));
}

__device__ __forceinline__ void mma_bf16(float* d, const uint32_t* a, const uint32_t* b) {
    asm volatile(
        "mma.sync.aligned.m16n8k16.row.col.f32.bf16.bf16.f32 "
        "{%0,%1,%2,%3}, {%4,%5,%6,%7}, {%8,%9}, {%0,%1,%2,%3};"
        : "+f"(d[0]), "+f"(d[1]), "+f"(d[2]), "+f"(d[3])
        : "r"(a[0]), "r"(a[1]), "r"(a[2]), "r"(a[3]), "r"(b[0]), "r"(b[1]));
}

#define CP_ASYNC16(dst, src) \
    asm volatile("cp.async.cg.shared.global [%0], [%1], 16;" \
                 :: "r"(dst), "l"(src) : "memory")
#define CP_COMMIT() asm volatile("cp.async.commit_group;" ::: "memory")
#define CP_WAIT2()  asm volatile("cp.async.wait_group 2;" ::: "memory")

// ---------------------------------------------------------------------------
// Split x into bf16 hi/lo (4 elems/thread)
// ---------------------------------------------------------------------------
__global__ void split_x_k(const float* __restrict__ x,
                          __nv_bfloat16* __restrict__ xh,
                          __nv_bfloat16* __restrict__ xl)
{
    size_t i = (size_t)blockIdx.x * 256 + threadIdx.x;
    float4 v = reinterpret_cast<const float4*>(x)[i];
    __nv_bfloat16 h0, h1, h2, h3, l0, l1, l2, l3;
    bf16_split(v.x, h0, l0);
    bf16_split(v.y, h1, l1);
    bf16_split(v.z, h2, l2);
    bf16_split(v.w, h3, l3);
    reinterpret_cast<__nv_bfloat162*>(xh)[2 * i]     = __nv_bfloat162(h0, h1);
    reinterpret_cast<__nv_bfloat162*>(xh)[2 * i + 1] = __nv_bfloat162(h2, h3);
    reinterpret_cast<__nv_bfloat162*>(xl)[2 * i]     = __nv_bfloat162(l0, l1);
    reinterpret_cast<__nv_bfloat162*>(xl)[2 * i + 1] = __nv_bfloat162(l2, l3);
}

// ---------------------------------------------------------------------------
// Transpose + bf16-split: W[K,N] -> oh/ol[Np,Kp] (zero padded)
// ---------------------------------------------------------------------------
__global__ void tsplit_k(const float* __restrict__ W, int K, int N,
                         int Kp, int Np,
                         __nv_bfloat16* __restrict__ oh,
                         __nv_bfloat16* __restrict__ ol)
{
    __shared__ float t[32][33];
    int k0 = blockIdx.x * 32, n0 = blockIdx.y * 32;
    int tx = threadIdx.x, ty = threadIdx.y;   // (32, 8)
#pragma unroll
    for (int i = 0; i < 4; i++) {
        int k = k0 + ty + i * 8, n = n0 + tx;
        t[ty + i * 8][tx] = (k < K && n < N) ? W[(size_t)k * N + n] : 0.f;
    }
    __syncthreads();
#pragma unroll
    for (int i = 0; i < 4; i++) {
        int n = n0 + ty + i * 8, k = k0 + tx;
        float v = t[tx][ty + i * 8];
        __nv_bfloat16 h, l;
        bf16_split(v, h, l);
        oh[(size_t)n * Kp + k] = h;
        ol[(size_t)n * Kp + k] = l;
    }
}

// ---------------------------------------------------------------------------
// bf16x3 tensor-core GEMM (mma.sync m16n8k16):
//   D[128,128] per CTA = (Ah+Al)[M,Kp] @ (Bh+Bl)[Np,Kp]^T
//   products: Ah·Bh + Ah·Bl + Al·Bh, fp32 accumulate.
// 4-stage cp.async pipeline. Smem rows padded to 24 halves (conflict-free).
// Epilogue: +bias (+ReLU); SPLITOUT -> bf16 hi/lo pair, else fp32 (col guard).
// ---------------------------------------------------------------------------
#define STAGES   4
#define STAGE_B  24576   // 4 operands * 128 rows * 48 B
#define ROWP     24      // padded row length in halves

template<bool RELU, bool SPLITOUT>
__global__ __launch_bounds__(256)
void mma_gemm(const __nv_bfloat16* __restrict__ Ah,
              const __nv_bfloat16* __restrict__ Al,
              const __nv_bfloat16* __restrict__ Bh,
              const __nv_bfloat16* __restrict__ Bl,
              const float* __restrict__ bias, int Nreal, int Kp,
              float* __restrict__ Of,
              __nv_bfloat16* __restrict__ Oh, __nv_bfloat16* __restrict__ Ol,
              int ldo)
{
    extern __shared__ char smem[];
    const int tid = threadIdx.x;
    const int wid = tid >> 5, lane = tid & 31;
    const int wm = wid & 1, wn = wid >> 1;        // warp grid 2 (M) x 4 (N)
    const int g = lane >> 2, t4 = lane & 3;
    const int bm = blockIdx.x * 128, bn = blockIdx.y * 128;
    const uint32_t sbase = smem_u32(smem);

    // cp.async loader coords: each thread loads one 16B chunk per operand
    const int lrow = tid >> 1;        // 0..127
    const int lhf = tid & 1;          // which 16B half of the 32B row
    const size_t aoff = (size_t)(bm + lrow) * Kp + lhf * 8;
    const size_t boff = (size_t)(bn + lrow) * Kp + lhf * 8;
    const uint32_t sdst = sbase + lrow * 48 + lhf * 16;

    auto load_stage = [&](int s, int k0) {
        uint32_t d = sdst + s * STAGE_B;
        CP_ASYNC16(d,             Ah + aoff + k0);
        CP_ASYNC16(d + 6144,      Al + aoff + k0);
        CP_ASYNC16(d + 12288,     Bh + boff + k0);
        CP_ASYNC16(d + 18432,     Bl + boff + k0);
    };

    float acc[4][4][4];
#pragma unroll
    for (int i = 0; i < 4; i++)
#pragma unroll
        for (int j = 0; j < 4; j++)
#pragma unroll
            for (int r = 0; r < 4; r++) acc[i][j][r] = 0.f;

    const int KT = Kp / 16;
#pragma unroll
    for (int s = 0; s < STAGES - 1; s++) {
        load_stage(s, s * 16);
        CP_COMMIT();
    }

    for (int kt = 0; kt < KT; kt++) {
        CP_WAIT2();
        __syncthreads();

        int ls = kt + STAGES - 1;
        if (ls < KT) load_stage(ls & (STAGES - 1), ls * 16);
        CP_COMMIT();

        const uint16_t* st = reinterpret_cast<const uint16_t*>(
            smem + (kt & (STAGES - 1)) * STAGE_B);
        const uint16_t* sAh = st;
        const uint16_t* sAl = st + 3072;
        const uint16_t* sBh = st + 6144;
        const uint16_t* sBl = st + 9216;

        uint32_t ah[4][4], al[4][4], bh[4][2], bl[4][2];
#pragma unroll
        for (int mf = 0; mf < 4; mf++) {
            int r0 = (wm * 64 + mf * 16 + g) * ROWP + 2 * t4;
            int r1 = r0 + 8 * ROWP;
            ah[mf][0] = *reinterpret_cast<const uint32_t*>(sAh + r0);
            ah[mf][1] = *reinterpret_cast<const uint32_t*>(sAh + r1);
            ah[mf][2] = *reinterpret_cast<const uint32_t*>(sAh + r0 + 8);
            ah[mf][3] = *reinterpret_cast<const uint32_t*>(sAh + r1 + 8);
            al[mf][0] = *reinterpret_cast<const uint32_t*>(sAl + r0);
            al[mf][1] = *reinterpret_cast<const uint32_t*>(sAl + r1);
            al[mf][2] = *reinterpret_cast<const uint32_t*>(sAl + r0 + 8);
            al[mf][3] = *reinterpret_cast<const uint32_t*>(sAl + r1 + 8);
        }
#pragma unroll
        for (int nf = 0; nf < 4; nf++) {
            int n0 = (wn * 32 + nf * 8 + g) * ROWP + 2 * t4;
            bh[nf][0] = *reinterpret_cast<const uint32_t*>(sBh + n0);
            bh[nf][1] = *reinterpret_cast<const uint32_t*>(sBh + n0 + 8);
            bl[nf][0] = *reinterpret_cast<const uint32_t*>(sBl + n0);
            bl[nf][1] = *reinterpret_cast<const uint32_t*>(sBl + n0 + 8);
        }
#pragma unroll
        for (int mf = 0; mf < 4; mf++)
#pragma unroll
            for (int nf = 0; nf < 4; nf++) {
                mma_bf16(acc[mf][nf], ah[mf], bh[nf]);
                mma_bf16(acc[mf][nf], ah[mf], bl[nf]);
                mma_bf16(acc[mf][nf], al[mf], bh[nf]);
            }
        __syncthreads();
    }

    // Epilogue
#pragma unroll
    for (int mf = 0; mf < 4; mf++)
#pragma unroll
        for (int nf = 0; nf < 4; nf++) {
            int row = bm + wm * 64 + mf * 16 + g;
            int col = bn + wn * 32 + nf * 8 + 2 * t4;
            const float* a = acc[mf][nf];
            float b0 = (col < Nreal) ? bias[col] : 0.f;
            float b1 = (col + 1 < Nreal) ? bias[col + 1] : 0.f;
#pragma unroll
            for (int h = 0; h < 2; h++) {
                int r = row + h * 8;
                float v0 = a[2 * h + 0] + b0;
                float v1 = a[2 * h + 1] + b1;
                if (RELU) { v0 = fmaxf(v0, 0.f); v1 = fmaxf(v1, 0.f); }
                if constexpr (SPLITOUT) {
                    __nv_bfloat16 h0, l0, h1, l1;
                    bf16_split(v0, h0, l0);
                    bf16_split(v1, h1, l1);
                    *reinterpret_cast<__nv_bfloat162*>(Oh + (size_t)r * ldo + col) =
                        __nv_bfloat162(h0, h1);
                    *reinterpret_cast<__nv_bfloat162*>(Ol + (size_t)r * ldo + col) =
                        __nv_bfloat162(l0, l1);
                } else {
                    if (col < Nreal)     Of[(size_t)r * ldo + col] = v0;
                    if (col + 1 < Nreal) Of[(size_t)r * ldo + col + 1] = v1;
                }
            }
        }
}

// ---------------------------------------------------------------------------
// Row-wise argmax over y1[B, C] -> idx[B] (first max on ties)
// ---------------------------------------------------------------------------
__global__ void argmax_rows(const float* __restrict__ y1, int* __restrict__ idx)
{
    int b = blockIdx.x * (blockDim.x >> 5) + (threadIdx.x >> 5);
    if (b >= B_) return;
    int lane = threadIdx.x & 31;
    float best = -__int_as_float(0x7f800000);
    int bi = C_;
    for (int c = lane; c < C_; c += 32) {
        float v = y1[(size_t)b * C_ + c];
        if (v > best) { best = v; bi = c; }
    }
#pragma unroll
    for (int off = 16; off; off >>= 1) {
        float ov = __shfl_down_sync(0xffffffffu, best, off);
        int   oi = __shfl_down_sync(0xffffffffu, bi, off);
        if (ov > best || (ov == best && oi < bi)) { best = ov; bi = oi; }
    }
    if (lane == 0) idx[b] = bi;
}

// ---------------------------------------------------------------------------
// Sort-by-expert machinery
// ---------------------------------------------------------------------------
__global__ void zero_cnt_k()
{
    int t = threadIdx.x;
    if (t < C_) g_cnt[t] = 0;
}
__global__ void hist_k(const int* __restrict__ idx)
{
    int b = blockIdx.x * 256 + threadIdx.x;
    if (b < B_) atomicAdd(&g_cnt[idx[b]], 1);
}
__global__ void scan_k()
{
    if (threadIdx.x == 0) {
        int a = 0;
        for (int c = 0; c < C_; c++) {
            g_off[c] = a;
            g_cur[c] = a;
            a += g_cnt[c];
        }
        g_off[C_] = a;
    }
}
__global__ void scat_k(const int* __restrict__ idx)
{
    int b = blockIdx.x * 256 + threadIdx.x;
    if (b < B_) {
        int p = atomicAdd(&g_cur[idx[b]], 1);
        g_rows[p] = b;
    }
}

// ---------------------------------------------------------------------------
// Category head: y0 = x @ Wcat + bcat. One warp per row.
// ---------------------------------------------------------------------------
__global__ __launch_bounds__(256)
void cat_head(const float* __restrict__ x, const float* __restrict__ Wcat,
              const float* __restrict__ bcat, float* __restrict__ y0)
{
    int b = blockIdx.x * 8 + (threadIdx.x >> 5);
    int lane = threadIdx.x & 31;
    const float* xr = x + (size_t)b * N0_;
    float acc[NCLS_];
#pragma unroll
    for (int j = 0; j < NCLS_; j++) acc[j] = 0.f;
    for (int n = lane; n < N0_; n += 32) {
        float xv = xr[n];
        const float* wr = Wcat + (size_t)n * NCLS_;
#pragma unroll
        for (int j = 0; j < NCLS_; j++)
            acc[j] = fmaf(xv, wr[j], acc[j]);
    }
#pragma unroll
    for (int j = 0; j < NCLS_; j++) {
#pragma unroll
        for (int off = 16; off; off >>= 1)
            acc[j] += __shfl_down_sync(0xffffffffu, acc[j], off);
    }
    if (lane == 0) {
#pragma unroll
        for (int j = 0; j < NCLS_; j++)
            y0[(size_t)b * NCLS_ + j] = acc[j] + bcat[j];
    }
}

// ---------------------------------------------------------------------------
// Grouped expert kernel: CTA = (expert c, chunk of up to 32 rows of c).
// ---------------------------------------------------------------------------
#define MROWS 32
#define BKE   32

__global__ __launch_bounds__(256)
void expert_group(const float* __restrict__ x,
                  const float* __restrict__ We1, const float* __restrict__ be1,
                  const float* __restrict__ We2, const float* __restrict__ be2,
                  float* __restrict__ y2)
{
    const int c = blockIdx.x;
    const int base = g_off[c] + blockIdx.y * MROWS;
    const int end = g_off[c + 1];
    if (base >= end) return;
    const int nr = min(MROWS, end - base);

    __shared__ float xs[MROWS][BKE];
    __shared__ float ws[BKE][128];
    __shared__ float he[MROWS][104];
    __shared__ int   rs[MROWS];

    const int tid = threadIdx.x;
    if (tid < MROWS) rs[tid] = (tid < nr) ? g_rows[base + tid] : -1;
    for (int i = tid; i < BKE * 28; i += 256) {
        int kk = i / 28, n = 100 + i % 28;
        ws[kk][n] = 0.f;
    }
    __syncthreads();

    const int tx = tid & 31;
    const int ty = tid >> 5;
    const int r_ld = tid >> 3;
    const int q_ld = tid & 7;
    const int row_ld = rs[r_ld];

    float acc[4][4];
#pragma unroll
    for (int i = 0; i < 4; i++)
#pragma unroll
        for (int j = 0; j < 4; j++) acc[i][j] = 0.f;

    const float* Wc = We1 + (size_t)c * (N0_ * N3_);

    for (int k0 = 0; k0 < N0_; k0 += BKE) {
        float4 v = make_float4(0.f, 0.f, 0.f, 0.f);
        if (row_ld >= 0)
            v = reinterpret_cast<const float4*>(x + (size_t)row_ld * N0_ + k0)[q_ld];
        *reinterpret_cast<float4*>(&xs[r_ld][q_ld * 4]) = v;

        for (int i = tid; i < BKE * N3_; i += 256) {
            int kk = i / N3_, n = i - kk * N3_;
            ws[kk][n] = Wc[(size_t)(k0 + kk) * N3_ + n];
        }
        __syncthreads();
#pragma unroll
        for (int kk = 0; kk < BKE; kk++) {
            float4 b4 = *reinterpret_cast<const float4*>(&ws[kk][tx * 4]);
            float a0 = xs[ty * 4 + 0][kk];
            float a1 = xs[ty * 4 + 1][kk];
            float a2 = xs[ty * 4 + 2][kk];
            float a3 = xs[ty * 4 + 3][kk];
            acc[0][0] = fmaf(a0, b4.x, acc[0][0]);
            acc[0][1] = fmaf(a0, b4.y, acc[0][1]);
            acc[0][2] = fmaf(a0, b4.z, acc[0][2]);
            acc[0][3] = fmaf(a0, b4.w, acc[0][3]);
            acc[1][0] = fmaf(a1, b4.x, acc[1][0]);
            acc[1][1] = fmaf(a1, b4.y, acc[1][1]);
            acc[1][2] = fmaf(a1, b4.z, acc[1][2]);
            acc[1][3] = fmaf(a1, b4.w, acc[1][3]);
            acc[2][0] = fmaf(a2, b4.x, acc[2][0]);
            acc[2][1] = fmaf(a2, b4.y, acc[2][1]);
            acc[2][2] = fmaf(a2, b4.z, acc[2][2]);
            acc[2][3] = fmaf(a2, b4.w, acc[2][3]);
            acc[3][0] = fmaf(a3, b4.x, acc[3][0]);
            acc[3][1] = fmaf(a3, b4.y, acc[3][1]);
            acc[3][2] = fmaf(a3, b4.z, acc[3][2]);
            acc[3][3] = fmaf(a3, b4.w, acc[3][3]);
        }
        __syncthreads();
    }

    if (tx < 25) {
        float4 bb = *reinterpret_cast<const float4*>(be1 + (size_t)c * N3_ + tx * 4);
#pragma unroll
        for (int i = 0; i < 4; i++) {
            he[ty * 4 + i][tx * 4 + 0] = fmaxf(acc[i][0] + bb.x, 0.f);
            he[ty * 4 + i][tx * 4 + 1] = fmaxf(acc[i][1] + bb.y, 0.f);
            he[ty * 4 + i][tx * 4 + 2] = fmaxf(acc[i][2] + bb.z, 0.f);
            he[ty * 4 + i][tx * 4 + 3] = fmaxf(acc[i][3] + bb.w, 0.f);
        }
    }
    __syncthreads();

    if (tid < MROWS * 4) {
        int r = tid >> 2, d = tid & 3;
        if (r < nr && d < NDIM_) {
            const float* W2 = We2 + (size_t)c * (N3_ * NDIM_) + d;
            float a = 0.f;
#pragma unroll 4
            for (int k = 0; k < N3_; k++)
                a = fmaf(he[r][k], W2[(size_t)k * NDIM_], a);
            y2[(size_t)rs[r] * NDIM_ + d] = a + be2[(size_t)c * NDIM_ + d];
        }
    }
}

// ---------------------------------------------------------------------------
extern "C" void kernel_launch(void* const* d_in, const int* in_sizes, int n_in,
                              void* d_out, int out_size)
{
    (void)in_sizes; (void)n_in; (void)out_size;
    const float* x    = (const float*)d_in[0];
    const float* Wcat = (const float*)d_in[1];
    const float* bcat = (const float*)d_in[2];
    const float* Wb1  = (const float*)d_in[3];
    const float* bb1  = (const float*)d_in[4];
    const float* Wb2  = (const float*)d_in[5];
    const float* bb2  = (const float*)d_in[6];
    const float* Wb3  = (const float*)d_in[7];
    const float* bb3  = (const float*)d_in[8];
    const float* We1  = (const float*)d_in[9];
    const float* be1  = (const float*)d_in[10];
    const float* We2  = (const float*)d_in[11];
    const float* be2  = (const float*)d_in[12];

    float* out = (float*)d_out;
    float* y0 = out;
    float* y1 = out + (size_t)B_ * NCLS_;
    float* y2 = out + (size_t)B_ * (NCLS_ + C_);

    __nv_bfloat16 *xh, *xl, *w1h, *w1l, *w2h, *w2l, *w3h, *w3l;
    __nv_bfloat16 *h1h, *h1l, *h2h, *h2l;
    int* idx;
    cudaGetSymbolAddress((void**)&xh, g_xh);
    cudaGetSymbolAddress((void**)&xl, g_xl);
    cudaGetSymbolAddress((void**)&w1h, g_w1h);
    cudaGetSymbolAddress((void**)&w1l, g_w1l);
    cudaGetSymbolAddress((void**)&w2h, g_w2h);
    cudaGetSymbolAddress((void**)&w2l, g_w2l);
    cudaGetSymbolAddress((void**)&w3h, g_w3h);
    cudaGetSymbolAddress((void**)&w3l, g_w3l);
    cudaGetSymbolAddress((void**)&h1h, g_h1h);
    cudaGetSymbolAddress((void**)&h1l, g_h1l);
    cudaGetSymbolAddress((void**)&h2h, g_h2h);
    cudaGetSymbolAddress((void**)&h2l, g_h2l);
    cudaGetSymbolAddress((void**)&idx, g_idx);

    const int SMEMB = STAGES * STAGE_B;   // 98304
    cudaFuncSetAttribute(mma_gemm<true, true>,
                         cudaFuncAttributeMaxDynamicSharedMemorySize, SMEMB);
    cudaFuncSetAttribute(mma_gemm<false, false>,
                         cudaFuncAttributeMaxDynamicSharedMemorySize, SMEMB);

    // Preprocess: bf16 splits (x) + transposed/split weights
    split_x_k<<<(B_ * N0_ / 4) / 256, 256>>>(x, xh, xl);
    tsplit_k<<<dim3(N0_ / 32, N1P / 32), dim3(32, 8)>>>(Wb1, N0_, N1_, N0_, N1P, w1h, w1l);
    tsplit_k<<<dim3(N1P / 32, N2P / 32), dim3(32, 8)>>>(Wb2, N1_, N2_, N1P, N2P, w2h, w2l);
    tsplit_k<<<dim3(N2P / 32, N3P / 32), dim3(32, 8)>>>(Wb3, N2_, N3_, N2P, N3P, w3h, w3l);

    // G1: h1 = relu(x @ Wb1 + bb1) -> bf16 hi/lo [4096,1024]
    mma_gemm<true, true><<<dim3(B_ / 128, N1P / 128), 256, SMEMB>>>(
        xh, xl, w1h, w1l, bb1, N1_, N0_, nullptr, h1h, h1l, N1P);
    // G2: h2 = relu(h1 @ Wb2 + bb2) -> bf16 hi/lo [4096,512]
    mma_gemm<true, true><<<dim3(B_ / 128, N2P / 128), 256, SMEMB>>>(
        h1h, h1l, w2h, w2l, bb2, N2_, N1P, nullptr, h2h, h2l, N2P);
    // G3: y1 = h2 @ Wb3 + bb3 -> fp32 [4096,100]
    mma_gemm<false, false><<<dim3(B_ / 128, 1), 256, SMEMB>>>(
        h2h, h2l, w3h, w3l, bb3, C_, N2P, y1, nullptr, nullptr, C_);

    // idx = argmax(y1)
    argmax_rows<<<B_ / 8, 256>>>(y1, idx);
    // group rows by expert
    zero_cnt_k<<<1, 128>>>();
    hist_k<<<B_ / 256, 256>>>(idx);
    scan_k<<<1, 32>>>();
    scat_k<<<B_ / 256, 256>>>(idx);
    // category head
    cat_head<<<B_ / 8, 256>>>(x, Wcat, bcat, y0);
    // grouped expert path
    expert_group<<<dim3(C_, B_ / MROWS), 256>>>(x, We1, be1, We2, be2, y2);
}